// round 1
// baseline (speedup 1.0000x reference)
#include <cuda_runtime.h>
#include <stdint.h>

#define BN_EPS 1e-5f

// ---------------------------------------------------------------------------
// Scratch (device globals; no allocation allowed in kernel_launch)
// ---------------------------------------------------------------------------
__device__ float g_h1[(size_t)64 * 32 * 112 * 112];   // conv1 out  (~103 MB)
__device__ float g_h2[(size_t)64 * 64 * 112 * 112];   // conv2 out  (~205 MB)
__device__ float g_h3[(size_t)64 * 128 * 56 * 56];    // conv3 out  (~103 MB)
__device__ float g_w1t[3 * 9 * 32];                   // ternarized+BN-folded, [ic][kh][kw][oc]
__device__ float g_w2t[32 * 9 * 64];
__device__ float g_w3t[64 * 9 * 128];
__device__ float g_bias1[32], g_bias2[64], g_bias3[128];
__device__ float g_wlq[10 * 128];                     // ternarized linear weight
__device__ float g_pool[64 * 128];

// ---------------------------------------------------------------------------
// Block-wide sum reduction (256 threads)
// ---------------------------------------------------------------------------
__device__ __forceinline__ float block_reduce_sum(float v, float* sbuf) {
    int tid = threadIdx.x;
    #pragma unroll
    for (int o = 16; o > 0; o >>= 1) v += __shfl_down_sync(0xffffffffu, v, o);
    if ((tid & 31) == 0) sbuf[tid >> 5] = v;
    __syncthreads();
    float r = 0.f;
    if (tid == 0) {
        #pragma unroll
        for (int i = 0; i < 8; i++) r += sbuf[i];
        sbuf[0] = r;
    }
    __syncthreads();
    r = sbuf[0];
    __syncthreads();
    return r;
}

// ---------------------------------------------------------------------------
// Prep: ternarize all 4 weight tensors, fold BN scale into conv weights,
// compute per-channel bias. One block per tensor.
// ---------------------------------------------------------------------------
__global__ void prep_kernel(
    const float* __restrict__ w1, const float* __restrict__ g1, const float* __restrict__ b1,
    const float* __restrict__ m1, const float* __restrict__ v1,
    const float* __restrict__ w2, const float* __restrict__ g2, const float* __restrict__ b2,
    const float* __restrict__ m2, const float* __restrict__ v2,
    const float* __restrict__ w3, const float* __restrict__ g3, const float* __restrict__ b3,
    const float* __restrict__ m3, const float* __restrict__ v3,
    const float* __restrict__ wl)
{
    __shared__ float sbuf[8];
    const int t = blockIdx.x;
    const float* w; int n, OC, IC;
    const float *g, *b, *m, *vv;
    float* dstw; float* dstb;
    if (t == 0)      { w = w1; n = 864;   OC = 32;  IC = 3;  g = g1; b = b1; m = m1; vv = v1; dstw = g_w1t; dstb = g_bias1; }
    else if (t == 1) { w = w2; n = 18432; OC = 64;  IC = 32; g = g2; b = b2; m = m2; vv = v2; dstw = g_w2t; dstb = g_bias2; }
    else if (t == 2) { w = w3; n = 73728; OC = 128; IC = 64; g = g3; b = b3; m = m3; vv = v3; dstw = g_w3t; dstb = g_bias3; }
    else             { w = wl; n = 1280;  OC = 0;   IC = 0;  g = b = m = vv = nullptr; dstw = g_wlq; dstb = nullptr; }

    const int tid = threadIdx.x;

    // pass 1: mean |w|
    float s = 0.f;
    for (int i = tid; i < n; i += blockDim.x) s += fabsf(w[i]);
    float tot = block_reduce_sum(s, sbuf);
    float delta = 0.7f * tot / (float)n;

    // pass 2: alpha = mean |w| over |w| > delta
    float ms = 0.f, cnt = 0.f;
    for (int i = tid; i < n; i += blockDim.x) {
        float a = fabsf(w[i]);
        if (a > delta) { ms += a; cnt += 1.f; }
    }
    float msum = block_reduce_sum(ms, sbuf);
    float csum = block_reduce_sum(cnt, sbuf);
    float alpha = msum / fmaxf(csum, 1.f);

    // pass 3: write quantized weights
    if (t < 3) {
        const int K = IC * 9;
        for (int i = tid; i < n; i += blockDim.x) {
            int o = i / K;
            int rem = i % K;                      // (ic*3+kh)*3+kw
            float wv = w[i];
            float q = (fabsf(wv) > delta) ? copysignf(alpha, wv) : 0.f;
            float inv = g[o] / sqrtf(vv[o] + BN_EPS);
            dstw[rem * OC + o] = q * inv;         // transposed [ic][kh][kw][oc], BN folded
        }
        if (tid < OC) {
            float inv = g[tid] / sqrtf(vv[tid] + BN_EPS);
            dstb[tid] = b[tid] - m[tid] * inv;
        }
    } else {
        for (int i = tid; i < n; i += blockDim.x) {
            float wv = w[i];
            dstw[i] = (fabsf(wv) > delta) ? copysignf(alpha, wv) : 0.f;
        }
    }
}

// ---------------------------------------------------------------------------
// Direct 3x3 conv (pad=1) + bias + ReLU, smem tiled, register tile 4px x 8oc.
// Weight layout: [ic][kh][kw][oc].  Thread org: ocg = tid&3, pg = tid>>2.
// blockDim.x must equal TOH*TOW.
// ---------------------------------------------------------------------------
template<int IC, int OC, int H, int W, int STRIDE, int TOH, int TOW, int ICC>
__global__ void conv3x3_bn_relu(const float* __restrict__ in, float* __restrict__ out,
                                const float* __restrict__ wt, const float* __restrict__ bias)
{
    constexpr int OH  = (H - 1) / STRIDE + 1;
    constexpr int OW  = (W - 1) / STRIDE + 1;
    constexpr int OCB = 32;
    constexpr int IH  = (TOH - 1) * STRIDE + 3;
    constexpr int IW  = (TOW - 1) * STRIDE + 3;
    constexpr int IWP = (IW & 1) ? IW : IW + 1;   // odd padded width vs bank conflicts
    constexpr int COLQ = TOW / 4;
    constexpr int NT  = TOH * TOW;

    __shared__ float s_in[ICC][IH][IWP];
    __shared__ __align__(16) float s_w[ICC * 9 * OCB];

    const int tid  = threadIdx.x;
    const int ocg  = tid & 3;
    const int pg   = tid >> 2;
    const int row  = pg / COLQ;
    const int colq = pg % COLQ;
    const int z    = blockIdx.z;
    const int n    = z / (OC / OCB);
    const int oc_base = (z % (OC / OCB)) * OCB;
    const int ih0  = blockIdx.y * TOH * STRIDE - 1;
    const int iw0  = blockIdx.x * TOW * STRIDE - 1;

    float acc[4][8];
    #pragma unroll
    for (int p = 0; p < 4; p++)
        #pragma unroll
        for (int j = 0; j < 8; j++) acc[p][j] = 0.f;

    for (int icb = 0; icb < IC; icb += ICC) {
        // load input tile (with zero padding)
        for (int i = tid; i < ICC * IH * IW; i += NT) {
            int ic = i / (IH * IW);
            int r  = (i / IW) % IH;
            int c  = i % IW;
            int ih = ih0 + r, iw = iw0 + c;
            float v = 0.f;
            if (ih >= 0 && ih < H && iw >= 0 && iw < W)
                v = in[(((size_t)n * IC + icb + ic) * H + ih) * W + iw];
            s_in[ic][r][c] = v;
        }
        // load weight tile
        for (int i = tid; i < ICC * 9 * OCB; i += NT) {
            int icl = i / (9 * OCB);
            int k   = (i / OCB) % 9;
            int oc  = i % OCB;
            s_w[(icl * 9 + k) * OCB + oc] = wt[((icb + icl) * 9 + k) * OC + oc_base + oc];
        }
        __syncthreads();

        for (int ic = 0; ic < ICC; ic++) {
            #pragma unroll
            for (int kh = 0; kh < 3; kh++) {
                #pragma unroll
                for (int kw = 0; kw < 3; kw++) {
                    float xv[4];
                    #pragma unroll
                    for (int p = 0; p < 4; p++)
                        xv[p] = s_in[ic][row * STRIDE + kh][(colq * 4 + p) * STRIDE + kw];
                    const float4* wp =
                        reinterpret_cast<const float4*>(&s_w[(ic * 9 + kh * 3 + kw) * OCB + ocg * 8]);
                    float4 wa = wp[0], wb = wp[1];
                    #pragma unroll
                    for (int p = 0; p < 4; p++) {
                        acc[p][0] += xv[p] * wa.x;
                        acc[p][1] += xv[p] * wa.y;
                        acc[p][2] += xv[p] * wa.z;
                        acc[p][3] += xv[p] * wa.w;
                        acc[p][4] += xv[p] * wb.x;
                        acc[p][5] += xv[p] * wb.y;
                        acc[p][6] += xv[p] * wb.z;
                        acc[p][7] += xv[p] * wb.w;
                    }
                }
            }
        }
        __syncthreads();
    }

    const int oh = blockIdx.y * TOH + row;
    const int ow = blockIdx.x * TOW + colq * 4;
    #pragma unroll
    for (int j = 0; j < 8; j++) {
        int oc = oc_base + ocg * 8 + j;
        float bv = bias[oc];
        float4 v;
        v.x = fmaxf(acc[0][j] + bv, 0.f);
        v.y = fmaxf(acc[1][j] + bv, 0.f);
        v.z = fmaxf(acc[2][j] + bv, 0.f);
        v.w = fmaxf(acc[3][j] + bv, 0.f);
        *reinterpret_cast<float4*>(&out[(((size_t)n * OC + oc) * OH + oh) * OW + ow]) = v;
    }
}

// ---------------------------------------------------------------------------
// Global average pool: [64,128,56,56] -> g_pool[64,128]
// grid (64, 8), 256 threads; each warp handles 2 channels.
// ---------------------------------------------------------------------------
__global__ void pool_kernel(const float* __restrict__ h3)
{
    const int n  = blockIdx.x;
    const int cg = blockIdx.y;
    const int wrp  = threadIdx.x >> 5;
    const int lane = threadIdx.x & 31;
    #pragma unroll
    for (int s = 0; s < 2; s++) {
        int c = cg * 16 + wrp * 2 + s;
        const float* p = h3 + ((size_t)n * 128 + c) * 3136;
        float sum = 0.f;
        for (int i = lane; i < 3136; i += 32) sum += p[i];
        #pragma unroll
        for (int o = 16; o > 0; o >>= 1) sum += __shfl_down_sync(0xffffffffu, sum, o);
        if (lane == 0) g_pool[n * 128 + c] = sum * (1.f / 3136.f);
    }
}

// ---------------------------------------------------------------------------
// Linear: out[n,j] = pool[n,:] . wlq[j,:] + bl[j]   (64x10)
// ---------------------------------------------------------------------------
__global__ void linear_kernel(const float* __restrict__ bl, float* __restrict__ out)
{
    int tid = blockIdx.x * blockDim.x + threadIdx.x;
    if (tid >= 640) return;
    int n = tid / 10, j = tid % 10;
    const float* hp = &g_pool[n * 128];
    const float* wp = &g_wlq[j * 128];
    float s = bl[j];
    #pragma unroll 8
    for (int c = 0; c < 128; c++) s += hp[c] * wp[c];
    out[tid] = s;
}

// ---------------------------------------------------------------------------
// Launch
// ---------------------------------------------------------------------------
extern "C" void kernel_launch(void* const* d_in, const int* in_sizes, int n_in,
                              void* d_out, int out_size)
{
    const float* x  = (const float*)d_in[0];
    const float* w1 = (const float*)d_in[1];
    const float* g1 = (const float*)d_in[2];
    const float* b1 = (const float*)d_in[3];
    const float* m1 = (const float*)d_in[4];
    const float* v1 = (const float*)d_in[5];
    const float* w2 = (const float*)d_in[6];
    const float* g2 = (const float*)d_in[7];
    const float* b2 = (const float*)d_in[8];
    const float* m2 = (const float*)d_in[9];
    const float* v2 = (const float*)d_in[10];
    const float* w3 = (const float*)d_in[11];
    const float* g3 = (const float*)d_in[12];
    const float* b3 = (const float*)d_in[13];
    const float* m3 = (const float*)d_in[14];
    const float* v3 = (const float*)d_in[15];
    const float* wl = (const float*)d_in[16];
    const float* bl = (const float*)d_in[17];

    float *h1, *h2, *h3, *w1t, *w2t, *w3t, *bb1, *bb2, *bb3;
    cudaGetSymbolAddress((void**)&h1, g_h1);
    cudaGetSymbolAddress((void**)&h2, g_h2);
    cudaGetSymbolAddress((void**)&h3, g_h3);
    cudaGetSymbolAddress((void**)&w1t, g_w1t);
    cudaGetSymbolAddress((void**)&w2t, g_w2t);
    cudaGetSymbolAddress((void**)&w3t, g_w3t);
    cudaGetSymbolAddress((void**)&bb1, g_bias1);
    cudaGetSymbolAddress((void**)&bb2, g_bias2);
    cudaGetSymbolAddress((void**)&bb3, g_bias3);

    // 1. ternarize + BN-fold all weights
    prep_kernel<<<4, 256>>>(w1, g1, b1, m1, v1,
                            w2, g2, b2, m2, v2,
                            w3, g3, b3, m3, v3, wl);

    // 2. conv1: 3->32, 224x224 s2 -> 112x112
    conv3x3_bn_relu<3, 32, 224, 224, 2, 8, 16, 3>
        <<<dim3(7, 14, 64), 128>>>(x, h1, w1t, bb1);

    // 3. conv2: 32->64, 112x112 s1
    conv3x3_bn_relu<32, 64, 112, 112, 1, 16, 16, 8>
        <<<dim3(7, 7, 128), 256>>>(h1, h2, w2t, bb2);

    // 4. conv3: 64->128, 112x112 s2 -> 56x56
    conv3x3_bn_relu<64, 128, 112, 112, 2, 8, 28, 8>
        <<<dim3(2, 7, 256), 224>>>(h2, h3, w3t, bb3);

    // 5. global average pool
    pool_kernel<<<dim3(64, 8), 256>>>(h3);

    // 6. linear head
    linear_kernel<<<3, 256>>>(bl, (float*)d_out);
}

// round 2
// speedup vs baseline: 1.1252x; 1.1252x over previous
#include <cuda_runtime.h>
#include <stdint.h>

#define BN_EPS 1e-5f
typedef unsigned long long u64;

// ---------------------------------------------------------------------------
// Scratch (device globals; no allocation allowed in kernel_launch)
// ---------------------------------------------------------------------------
__device__ float g_h1[(size_t)64 * 32 * 112 * 112];   // conv1 out  (~103 MB)
__device__ float g_h2[(size_t)64 * 64 * 112 * 112];   // conv2 out  (~205 MB)
__device__ float g_h3[(size_t)64 * 128 * 56 * 56];    // conv3 out  (~103 MB)
__device__ float g_w1t[3 * 9 * 32];                   // ternarized+BN-folded, [ic][kh][kw][oc]
__device__ float g_w2t[32 * 9 * 64];
__device__ float g_w3t[64 * 9 * 128];
__device__ float g_bias1[32], g_bias2[64], g_bias3[128];
__device__ float g_wlq[10 * 128];                     // ternarized linear weight
__device__ float g_pool[64 * 128];

// ---------------------------------------------------------------------------
// f32x2 packed helpers (sm_103a)
// ---------------------------------------------------------------------------
__device__ __forceinline__ void fma2(u64& d, u64 a, u64 b) {
    asm("fma.rn.f32x2 %0, %1, %2, %3;" : "=l"(d) : "l"(a), "l"(b), "l"(d));
}
__device__ __forceinline__ u64 bcast2(float x) {
    u64 r;
    asm("mov.b64 %0, {%1, %1};" : "=l"(r) : "r"(__float_as_uint(x)));
    return r;
}
__device__ __forceinline__ void unpack2(u64 v, float& lo, float& hi) {
    unsigned int l, h;
    asm("mov.b64 {%0, %1}, %2;" : "=r"(l), "=r"(h) : "l"(v));
    lo = __uint_as_float(l); hi = __uint_as_float(h);
}

// ---------------------------------------------------------------------------
// Block-wide sum reduction (256 threads)
// ---------------------------------------------------------------------------
__device__ __forceinline__ float block_reduce_sum(float v, float* sbuf) {
    int tid = threadIdx.x;
    #pragma unroll
    for (int o = 16; o > 0; o >>= 1) v += __shfl_down_sync(0xffffffffu, v, o);
    if ((tid & 31) == 0) sbuf[tid >> 5] = v;
    __syncthreads();
    float r = 0.f;
    if (tid == 0) {
        #pragma unroll
        for (int i = 0; i < 8; i++) r += sbuf[i];
        sbuf[0] = r;
    }
    __syncthreads();
    r = sbuf[0];
    __syncthreads();
    return r;
}

// ---------------------------------------------------------------------------
// Prep: ternarize all 4 weight tensors, fold BN scale into conv weights,
// compute per-channel bias. One block per tensor.
// ---------------------------------------------------------------------------
__global__ void prep_kernel(
    const float* __restrict__ w1, const float* __restrict__ g1, const float* __restrict__ b1,
    const float* __restrict__ m1, const float* __restrict__ v1,
    const float* __restrict__ w2, const float* __restrict__ g2, const float* __restrict__ b2,
    const float* __restrict__ m2, const float* __restrict__ v2,
    const float* __restrict__ w3, const float* __restrict__ g3, const float* __restrict__ b3,
    const float* __restrict__ m3, const float* __restrict__ v3,
    const float* __restrict__ wl)
{
    __shared__ float sbuf[8];
    const int t = blockIdx.x;
    const float* w; int n, OC, IC;
    const float *g, *b, *m, *vv;
    float* dstw; float* dstb;
    if (t == 0)      { w = w1; n = 864;   OC = 32;  IC = 3;  g = g1; b = b1; m = m1; vv = v1; dstw = g_w1t; dstb = g_bias1; }
    else if (t == 1) { w = w2; n = 18432; OC = 64;  IC = 32; g = g2; b = b2; m = m2; vv = v2; dstw = g_w2t; dstb = g_bias2; }
    else if (t == 2) { w = w3; n = 73728; OC = 128; IC = 64; g = g3; b = b3; m = m3; vv = v3; dstw = g_w3t; dstb = g_bias3; }
    else             { w = wl; n = 1280;  OC = 0;   IC = 0;  g = b = m = vv = nullptr; dstw = g_wlq; dstb = nullptr; }

    const int tid = threadIdx.x;

    // pass 1: mean |w|
    float s = 0.f;
    for (int i = tid; i < n; i += blockDim.x) s += fabsf(w[i]);
    float tot = block_reduce_sum(s, sbuf);
    float delta = 0.7f * tot / (float)n;

    // pass 2: alpha = mean |w| over |w| > delta
    float ms = 0.f, cnt = 0.f;
    for (int i = tid; i < n; i += blockDim.x) {
        float a = fabsf(w[i]);
        if (a > delta) { ms += a; cnt += 1.f; }
    }
    float msum = block_reduce_sum(ms, sbuf);
    float csum = block_reduce_sum(cnt, sbuf);
    float alpha = msum / fmaxf(csum, 1.f);

    // pass 3: write quantized weights
    if (t < 3) {
        const int K = IC * 9;
        for (int i = tid; i < n; i += blockDim.x) {
            int o = i / K;
            int rem = i % K;                      // (ic*3+kh)*3+kw
            float wv = w[i];
            float q = (fabsf(wv) > delta) ? copysignf(alpha, wv) : 0.f;
            float inv = g[o] / sqrtf(vv[o] + BN_EPS);
            dstw[rem * OC + o] = q * inv;         // transposed [ic][kh][kw][oc], BN folded
        }
        if (tid < OC) {
            float inv = g[tid] / sqrtf(vv[tid] + BN_EPS);
            dstb[tid] = b[tid] - m[tid] * inv;
        }
    } else {
        for (int i = tid; i < n; i += blockDim.x) {
            float wv = w[i];
            dstw[i] = (fabsf(wv) > delta) ? copysignf(alpha, wv) : 0.f;
        }
    }
}

// ---------------------------------------------------------------------------
// conv1 only: scalar direct 3x3 conv (pad=1) + bias + ReLU (IC=3, cheap)
// ---------------------------------------------------------------------------
template<int IC, int OC, int H, int W, int STRIDE, int TOH, int TOW, int ICC>
__global__ void conv3x3_scalar(const float* __restrict__ in, float* __restrict__ out,
                               const float* __restrict__ wt, const float* __restrict__ bias)
{
    constexpr int OH  = (H - 1) / STRIDE + 1;
    constexpr int OW  = (W - 1) / STRIDE + 1;
    constexpr int OCB = 32;
    constexpr int IH  = (TOH - 1) * STRIDE + 3;
    constexpr int IW  = (TOW - 1) * STRIDE + 3;
    constexpr int IWP = (IW & 1) ? IW : IW + 1;
    constexpr int COLQ = TOW / 4;
    constexpr int NT  = TOH * TOW;

    __shared__ float s_in[ICC][IH][IWP];
    __shared__ __align__(16) float s_w[ICC * 9 * OCB];

    const int tid  = threadIdx.x;
    const int ocg  = tid & 3;
    const int pg   = tid >> 2;
    const int row  = pg / COLQ;
    const int colq = pg % COLQ;
    const int z    = blockIdx.z;
    const int n    = z / (OC / OCB);
    const int oc_base = (z % (OC / OCB)) * OCB;
    const int ih0  = blockIdx.y * TOH * STRIDE - 1;
    const int iw0  = blockIdx.x * TOW * STRIDE - 1;

    float acc[4][8];
    #pragma unroll
    for (int p = 0; p < 4; p++)
        #pragma unroll
        for (int j = 0; j < 8; j++) acc[p][j] = 0.f;

    for (int icb = 0; icb < IC; icb += ICC) {
        for (int i = tid; i < ICC * IH * IW; i += NT) {
            int ic = i / (IH * IW);
            int r  = (i / IW) % IH;
            int c  = i % IW;
            int ih = ih0 + r, iw = iw0 + c;
            float v = 0.f;
            if (ih >= 0 && ih < H && iw >= 0 && iw < W)
                v = in[(((size_t)n * IC + icb + ic) * H + ih) * W + iw];
            s_in[ic][r][c] = v;
        }
        for (int i = tid; i < ICC * 9 * OCB; i += NT) {
            int icl = i / (9 * OCB);
            int k   = (i / OCB) % 9;
            int oc  = i % OCB;
            s_w[(icl * 9 + k) * OCB + oc] = wt[((icb + icl) * 9 + k) * OC + oc_base + oc];
        }
        __syncthreads();

        for (int ic = 0; ic < ICC; ic++) {
            #pragma unroll
            for (int kh = 0; kh < 3; kh++) {
                #pragma unroll
                for (int kw = 0; kw < 3; kw++) {
                    float xv[4];
                    #pragma unroll
                    for (int p = 0; p < 4; p++)
                        xv[p] = s_in[ic][row * STRIDE + kh][(colq * 4 + p) * STRIDE + kw];
                    const float4* wp =
                        reinterpret_cast<const float4*>(&s_w[(ic * 9 + kh * 3 + kw) * OCB + ocg * 8]);
                    float4 wa = wp[0], wb = wp[1];
                    #pragma unroll
                    for (int p = 0; p < 4; p++) {
                        acc[p][0] += xv[p] * wa.x;
                        acc[p][1] += xv[p] * wa.y;
                        acc[p][2] += xv[p] * wa.z;
                        acc[p][3] += xv[p] * wa.w;
                        acc[p][4] += xv[p] * wb.x;
                        acc[p][5] += xv[p] * wb.y;
                        acc[p][6] += xv[p] * wb.z;
                        acc[p][7] += xv[p] * wb.w;
                    }
                }
            }
        }
        __syncthreads();
    }

    const int oh = blockIdx.y * TOH + row;
    const int ow = blockIdx.x * TOW + colq * 4;
    #pragma unroll
    for (int j = 0; j < 8; j++) {
        int oc = oc_base + ocg * 8 + j;
        float bv = bias[oc];
        float4 v;
        v.x = fmaxf(acc[0][j] + bv, 0.f);
        v.y = fmaxf(acc[1][j] + bv, 0.f);
        v.z = fmaxf(acc[2][j] + bv, 0.f);
        v.w = fmaxf(acc[3][j] + bv, 0.f);
        *reinterpret_cast<float4*>(&out[(((size_t)n * OC + oc) * OH + oh) * OW + ow]) = v;
    }
}

// ---------------------------------------------------------------------------
// conv2/conv3: f32x2-packed direct 3x3 conv (pad=1) + bias + ReLU.
// Register tile per thread: 4 px x 8 oc, held as 4 px x 4 oc-PAIRS (u64).
// Weight pairs come straight from LDS.128 of [k][oc] tile (consecutive oc).
// Input values broadcast-packed once per (ic,kh).
// Weight layout: [ic][kh][kw][oc].  blockDim = TOH*(TOW/4)*4.
// ---------------------------------------------------------------------------
template<int IC, int OC, int H, int W, int STRIDE, int TOH, int TOW, int ICC, int NT>
__global__ void __launch_bounds__(NT, 2)
conv3x3_f32x2(const float* __restrict__ in, float* __restrict__ out,
              const float* __restrict__ wt, const float* __restrict__ bias)
{
    constexpr int OH  = (H - 1) / STRIDE + 1;
    constexpr int OW  = (W - 1) / STRIDE + 1;
    constexpr int OCB = 32;
    constexpr int IH  = (TOH - 1) * STRIDE + 3;
    constexpr int IW  = (TOW - 1) * STRIDE + 3;
    constexpr int IWP = ((IW + 3) / 4) * 4 + ((((IW + 3) / 4) * 4 == IW) ? 4 : 0); // mult of 4, > IW headroom below
    constexpr int COLQ = TOW / 4;
    constexpr int NX  = 3 * STRIDE + 3;   // distinct input cols per (ic,kh): 6 (s1) / 9 (s2)
    constexpr int NV  = (NX + 3) / 4;     // float4 loads: 2 / 3

    static_assert(NT == TOH * COLQ * 4, "thread count mismatch");
    // float4 read span check: colq_max*4*S + NV*4 <= IWP
    static_assert((COLQ - 1) * 4 * STRIDE + NV * 4 <= IWP, "smem row overrun");

    __shared__ __align__(16) float s_in[ICC][IH][IWP];
    __shared__ __align__(16) float s_w[ICC * 9 * OCB];

    const int tid  = threadIdx.x;
    const int ocg  = tid & 3;
    const int pg   = tid >> 2;
    const int row  = pg / COLQ;
    const int colq = pg % COLQ;
    const int z    = blockIdx.z;
    const int n    = z / (OC / OCB);
    const int oc_base = (z % (OC / OCB)) * OCB;
    const int ih0  = blockIdx.y * TOH * STRIDE - 1;
    const int iw0  = blockIdx.x * TOW * STRIDE - 1;

    u64 acc[4][4];    // [px][oc_pair]
    #pragma unroll
    for (int p = 0; p < 4; p++)
        #pragma unroll
        for (int j = 0; j < 4; j++) acc[p][j] = 0ull;

    for (int icb = 0; icb < IC; icb += ICC) {
        // stage input tile (zero-padded borders)
        for (int i = tid; i < ICC * IH * IW; i += NT) {
            int ic = i / (IH * IW);
            int r  = (i / IW) % IH;
            int c  = i % IW;
            int ih = ih0 + r, iw = iw0 + c;
            float v = 0.f;
            if (ih >= 0 && ih < H && iw >= 0 && iw < W)
                v = in[(((size_t)n * IC + icb + ic) * H + ih) * W + iw];
            s_in[ic][r][c] = v;
        }
        // stage weight tile
        for (int i = tid; i < ICC * 9 * OCB; i += NT) {
            int icl = i / (9 * OCB);
            int k   = (i / OCB) % 9;
            int oc  = i % OCB;
            s_w[(icl * 9 + k) * OCB + oc] = wt[((icb + icl) * 9 + k) * OC + oc_base + oc];
        }
        __syncthreads();

        #pragma unroll
        for (int ic = 0; ic < ICC; ic++) {
            #pragma unroll
            for (int kh = 0; kh < 3; kh++) {
                const float* xr = &s_in[ic][row * STRIDE + kh][colq * 4 * STRIDE];
                float xf[NV * 4];
                #pragma unroll
                for (int q = 0; q < NV; q++)
                    *reinterpret_cast<float4*>(&xf[q * 4]) =
                        reinterpret_cast<const float4*>(xr)[q];
                u64 xb[NX];
                #pragma unroll
                for (int i = 0; i < NX; i++) xb[i] = bcast2(xf[i]);

                #pragma unroll
                for (int kw = 0; kw < 3; kw++) {
                    const ulonglong2* wp = reinterpret_cast<const ulonglong2*>(
                        &s_w[(ic * 9 + kh * 3 + kw) * OCB + ocg * 8]);
                    ulonglong2 wa = wp[0], wb2 = wp[1];
                    #pragma unroll
                    for (int p = 0; p < 4; p++) {
                        u64 xv = xb[p * STRIDE + kw];
                        fma2(acc[p][0], xv, wa.x);
                        fma2(acc[p][1], xv, wa.y);
                        fma2(acc[p][2], xv, wb2.x);
                        fma2(acc[p][3], xv, wb2.y);
                    }
                }
            }
        }
        __syncthreads();
    }

    // epilogue: unpack, bias, relu, store float4 per oc
    const int oh = blockIdx.y * TOH + row;
    const int ow = blockIdx.x * TOW + colq * 4;
    #pragma unroll
    for (int jp = 0; jp < 4; jp++) {
        float lo[4], hi[4];
        #pragma unroll
        for (int p = 0; p < 4; p++) unpack2(acc[p][jp], lo[p], hi[p]);
        int oc0 = oc_base + ocg * 8 + jp * 2;
        float b0 = bias[oc0], b1 = bias[oc0 + 1];
        float4 v0, v1;
        v0.x = fmaxf(lo[0] + b0, 0.f); v0.y = fmaxf(lo[1] + b0, 0.f);
        v0.z = fmaxf(lo[2] + b0, 0.f); v0.w = fmaxf(lo[3] + b0, 0.f);
        v1.x = fmaxf(hi[0] + b1, 0.f); v1.y = fmaxf(hi[1] + b1, 0.f);
        v1.z = fmaxf(hi[2] + b1, 0.f); v1.w = fmaxf(hi[3] + b1, 0.f);
        *reinterpret_cast<float4*>(&out[(((size_t)n * OC + oc0) * OH + oh) * OW + ow]) = v0;
        *reinterpret_cast<float4*>(&out[(((size_t)n * OC + oc0 + 1) * OH + oh) * OW + ow]) = v1;
    }
}

// ---------------------------------------------------------------------------
// Global average pool: [64,128,56,56] -> g_pool[64,128]
// ---------------------------------------------------------------------------
__global__ void pool_kernel(const float* __restrict__ h3)
{
    const int n  = blockIdx.x;
    const int cg = blockIdx.y;
    const int wrp  = threadIdx.x >> 5;
    const int lane = threadIdx.x & 31;
    #pragma unroll
    for (int s = 0; s < 2; s++) {
        int c = cg * 16 + wrp * 2 + s;
        const float* p = h3 + ((size_t)n * 128 + c) * 3136;
        float sum = 0.f;
        for (int i = lane; i < 3136; i += 32) sum += p[i];
        #pragma unroll
        for (int o = 16; o > 0; o >>= 1) sum += __shfl_down_sync(0xffffffffu, sum, o);
        if (lane == 0) g_pool[n * 128 + c] = sum * (1.f / 3136.f);
    }
}

// ---------------------------------------------------------------------------
// Linear: out[n,j] = pool[n,:] . wlq[j,:] + bl[j]   (64x10)
// ---------------------------------------------------------------------------
__global__ void linear_kernel(const float* __restrict__ bl, float* __restrict__ out)
{
    int tid = blockIdx.x * blockDim.x + threadIdx.x;
    if (tid >= 640) return;
    int n = tid / 10, j = tid % 10;
    const float* hp = &g_pool[n * 128];
    const float* wp = &g_wlq[j * 128];
    float s = bl[j];
    #pragma unroll 8
    for (int c = 0; c < 128; c++) s += hp[c] * wp[c];
    out[tid] = s;
}

// ---------------------------------------------------------------------------
// Launch
// ---------------------------------------------------------------------------
extern "C" void kernel_launch(void* const* d_in, const int* in_sizes, int n_in,
                              void* d_out, int out_size)
{
    const float* x  = (const float*)d_in[0];
    const float* w1 = (const float*)d_in[1];
    const float* g1 = (const float*)d_in[2];
    const float* b1 = (const float*)d_in[3];
    const float* m1 = (const float*)d_in[4];
    const float* v1 = (const float*)d_in[5];
    const float* w2 = (const float*)d_in[6];
    const float* g2 = (const float*)d_in[7];
    const float* b2 = (const float*)d_in[8];
    const float* m2 = (const float*)d_in[9];
    const float* v2 = (const float*)d_in[10];
    const float* w3 = (const float*)d_in[11];
    const float* g3 = (const float*)d_in[12];
    const float* b3 = (const float*)d_in[13];
    const float* m3 = (const float*)d_in[14];
    const float* v3 = (const float*)d_in[15];
    const float* wl = (const float*)d_in[16];
    const float* bl = (const float*)d_in[17];

    float *h1, *h2, *h3, *w1t, *w2t, *w3t, *bb1, *bb2, *bb3;
    cudaGetSymbolAddress((void**)&h1, g_h1);
    cudaGetSymbolAddress((void**)&h2, g_h2);
    cudaGetSymbolAddress((void**)&h3, g_h3);
    cudaGetSymbolAddress((void**)&w1t, g_w1t);
    cudaGetSymbolAddress((void**)&w2t, g_w2t);
    cudaGetSymbolAddress((void**)&w3t, g_w3t);
    cudaGetSymbolAddress((void**)&bb1, g_bias1);
    cudaGetSymbolAddress((void**)&bb2, g_bias2);
    cudaGetSymbolAddress((void**)&bb3, g_bias3);

    // 1. ternarize + BN-fold all weights
    prep_kernel<<<4, 256>>>(w1, g1, b1, m1, v1,
                            w2, g2, b2, m2, v2,
                            w3, g3, b3, m3, v3, wl);

    // 2. conv1: 3->32, 224x224 s2 -> 112x112 (scalar path, 2% of FLOPs)
    conv3x3_scalar<3, 32, 224, 224, 2, 8, 16, 3>
        <<<dim3(7, 14, 64), 128>>>(x, h1, w1t, bb1);

    // 3. conv2: 32->64, 112x112 s1 (f32x2 path)
    conv3x3_f32x2<32, 64, 112, 112, 1, 16, 16, 8, 256>
        <<<dim3(7, 7, 128), 256>>>(h1, h2, w2t, bb2);

    // 4. conv3: 64->128, 112x112 s2 -> 56x56 (f32x2 path)
    conv3x3_f32x2<64, 128, 112, 112, 2, 8, 28, 8, 224>
        <<<dim3(2, 7, 256), 224>>>(h2, h3, w3t, bb3);

    // 5. global average pool
    pool_kernel<<<dim3(64, 8), 256>>>(h3);

    // 6. linear head
    linear_kernel<<<3, 256>>>(bl, (float*)d_out);
}

// round 5
// speedup vs baseline: 2.9401x; 2.6129x over previous
#include <cuda_runtime.h>
#include <cuda_bf16.h>
#include <stdint.h>

#define BN_EPS 1e-5f

// ---------------------------------------------------------------------------
// Device-global scratch (no allocations allowed)
// ---------------------------------------------------------------------------
__device__ __nv_bfloat16 g_h1[(size_t)64 * 112 * 112 * 32];   // conv1 out, NHWC bf16 (51MB)
__device__ __nv_bfloat16 g_h2[(size_t)64 * 112 * 112 * 64];   // conv2 out, NHWC bf16 (103MB)
__device__ __nv_bfloat16 g_h3[(size_t)64 * 56 * 56 * 128];    // conv3 out, NHWC bf16 (51MB)
__device__ float         g_w1t[27 * 32];                      // conv1 folded fp32 [k][oc]
__device__ __nv_bfloat16 g_wsgn2[64 * 288];                   // conv2 signs [oc][k], k=tap*32+ic
__device__ __nv_bfloat16 g_wsgn3[128 * 576];                  // conv3 signs [oc][k], k=tap*64+ic
__device__ float g_bias1[32];
__device__ float g_scale2[64],  g_bias2[64];
__device__ float g_scale3[128], g_bias3[128];
__device__ float g_wlq[10 * 128];
__device__ float g_pool[64 * 128];

// ---------------------------------------------------------------------------
// PTX helpers (base ISA only — no 'a'-suffix features)
// ---------------------------------------------------------------------------
__device__ __forceinline__ uint32_t smem_u32(const void* p) {
    uint32_t a;
    asm("{ .reg .u64 t; cvta.to.shared.u64 t, %1; cvt.u32.u64 %0, t; }" : "=r"(a) : "l"(p));
    return a;
}
__device__ __forceinline__ void ldmatrix_x4(uint32_t* r, uint32_t addr) {
    asm volatile("ldmatrix.sync.aligned.m8n8.x4.shared.b16 {%0,%1,%2,%3}, [%4];"
        : "=r"(r[0]), "=r"(r[1]), "=r"(r[2]), "=r"(r[3]) : "r"(addr));
}
__device__ __forceinline__ void ldmatrix_x2(uint32_t* r, uint32_t addr) {
    asm volatile("ldmatrix.sync.aligned.m8n8.x2.shared.b16 {%0,%1}, [%2];"
        : "=r"(r[0]), "=r"(r[1]) : "r"(addr));
}
__device__ __forceinline__ void mma16816(float* c, const uint32_t* a, const uint32_t* b) {
    asm volatile("mma.sync.aligned.m16n8k16.row.col.f32.bf16.bf16.f32 "
        "{%0,%1,%2,%3}, {%4,%5,%6,%7}, {%8,%9}, {%0,%1,%2,%3};"
        : "+f"(c[0]), "+f"(c[1]), "+f"(c[2]), "+f"(c[3])
        : "r"(a[0]), "r"(a[1]), "r"(a[2]), "r"(a[3]), "r"(b[0]), "r"(b[1]));
}
__device__ __forceinline__ uint32_t pack_bf16x2(float lo, float hi) {
    uint32_t r;
    asm("cvt.rn.bf16x2.f32 %0, %1, %2;" : "=r"(r) : "f"(hi), "f"(lo));
    return r;
}

// ---------------------------------------------------------------------------
// Block-wide sum reduction (256 threads)
// ---------------------------------------------------------------------------
__device__ __forceinline__ float block_reduce_sum(float v, float* sbuf) {
    int tid = threadIdx.x;
    #pragma unroll
    for (int o = 16; o > 0; o >>= 1) v += __shfl_down_sync(0xffffffffu, v, o);
    if ((tid & 31) == 0) sbuf[tid >> 5] = v;
    __syncthreads();
    float r = 0.f;
    if (tid == 0) {
        #pragma unroll
        for (int i = 0; i < 8; i++) r += sbuf[i];
        sbuf[0] = r;
    }
    __syncthreads();
    r = sbuf[0];
    __syncthreads();
    return r;
}

// ---------------------------------------------------------------------------
// Prep: ternarize weights. conv1 -> folded fp32 [k][oc]; conv2/3 -> bf16 sign
// matrices [oc][K] with k=(kh*3+kw)*IC+ic; fp32 scale/bias arrays.
// ---------------------------------------------------------------------------
__global__ void prep_kernel(
    const float* __restrict__ w1, const float* __restrict__ g1, const float* __restrict__ b1,
    const float* __restrict__ m1, const float* __restrict__ v1,
    const float* __restrict__ w2, const float* __restrict__ g2, const float* __restrict__ b2,
    const float* __restrict__ m2, const float* __restrict__ v2,
    const float* __restrict__ w3, const float* __restrict__ g3, const float* __restrict__ b3,
    const float* __restrict__ m3, const float* __restrict__ v3,
    const float* __restrict__ wl)
{
    __shared__ float sbuf[8];
    const int t = blockIdx.x;
    const float* w; int n;
    if (t == 0)      { w = w1; n = 864;   }
    else if (t == 1) { w = w2; n = 18432; }
    else if (t == 2) { w = w3; n = 73728; }
    else             { w = wl; n = 1280;  }

    const int tid = threadIdx.x;

    float s = 0.f;
    for (int i = tid; i < n; i += blockDim.x) s += fabsf(w[i]);
    float tot = block_reduce_sum(s, sbuf);
    float delta = 0.7f * tot / (float)n;

    float ms = 0.f, cnt = 0.f;
    for (int i = tid; i < n; i += blockDim.x) {
        float a = fabsf(w[i]);
        if (a > delta) { ms += a; cnt += 1.f; }
    }
    float msum = block_reduce_sum(ms, sbuf);
    float csum = block_reduce_sum(cnt, sbuf);
    float alpha = msum / fmaxf(csum, 1.f);

    if (t == 0) {
        for (int i = tid; i < n; i += blockDim.x) {
            int o = i / 27, rem = i % 27;           // rem = ic*9+kh*3+kw
            float wv = w[i];
            float q = (fabsf(wv) > delta) ? copysignf(alpha, wv) : 0.f;
            float inv = g1[o] * rsqrtf(v1[o] + BN_EPS);
            g_w1t[rem * 32 + o] = q * inv;
        }
        if (tid < 32) {
            float inv = g1[tid] * rsqrtf(v1[tid] + BN_EPS);
            g_bias1[tid] = b1[tid] - m1[tid] * inv;
        }
    } else if (t == 1) {
        for (int i = tid; i < 64 * 288; i += blockDim.x) {
            int o = i / 288, k = i % 288;
            int tap = k / 32, ic = k % 32;
            float wv = w2[o * 288 + ic * 9 + tap];
            float sv = (fabsf(wv) > delta) ? ((wv > 0.f) ? 1.f : -1.f) : 0.f;
            g_wsgn2[i] = __float2bfloat16(sv);
        }
        if (tid < 64) {
            float inv = g2[tid] * rsqrtf(v2[tid] + BN_EPS);
            g_scale2[tid] = alpha * inv;
            g_bias2[tid]  = b2[tid] - m2[tid] * inv;
        }
    } else if (t == 2) {
        for (int i = tid; i < 128 * 576; i += blockDim.x) {
            int o = i / 576, k = i % 576;
            int tap = k / 64, ic = k % 64;
            float wv = w3[o * 576 + ic * 9 + tap];
            float sv = (fabsf(wv) > delta) ? ((wv > 0.f) ? 1.f : -1.f) : 0.f;
            g_wsgn3[i] = __float2bfloat16(sv);
        }
        if (tid < 128) {
            float inv = g3[tid] * rsqrtf(v3[tid] + BN_EPS);
            g_scale3[tid] = alpha * inv;
            g_bias3[tid]  = b3[tid] - m3[tid] * inv;
        }
    } else {
        for (int i = tid; i < n; i += blockDim.x) {
            float wv = w[i];
            g_wlq[i] = (fabsf(wv) > delta) ? copysignf(alpha, wv) : 0.f;
        }
    }
}

// ---------------------------------------------------------------------------
// conv1: scalar fp32 direct 3x3 s2 (IC=3), NCHW fp32 in -> NHWC bf16 out
// ---------------------------------------------------------------------------
__global__ void conv1_kernel(const float* __restrict__ in, __nv_bfloat16* __restrict__ out,
                             const float* __restrict__ wt, const float* __restrict__ bias)
{
    constexpr int IC = 3, OC = 32, H = 224, W = 224, S = 2, TOH = 8, TOW = 16;
    constexpr int OH = 112, OW = 112;
    constexpr int IH = (TOH - 1) * S + 3;     // 17
    constexpr int IW = (TOW - 1) * S + 3;     // 33
    constexpr int COLQ = TOW / 4;
    constexpr int NT = 128;

    __shared__ float s_in[IC][IH][IW];
    __shared__ __align__(16) float s_w[IC * 9 * OC];

    const int tid  = threadIdx.x;
    const int ocg  = tid & 3;
    const int pg   = tid >> 2;
    const int row  = pg / COLQ;
    const int colq = pg % COLQ;
    const int n    = blockIdx.z;
    const int ih0  = blockIdx.y * TOH * S - 1;
    const int iw0  = blockIdx.x * TOW * S - 1;

    float acc[4][8];
    #pragma unroll
    for (int p = 0; p < 4; p++)
        #pragma unroll
        for (int j = 0; j < 8; j++) acc[p][j] = 0.f;

    for (int i = tid; i < IC * IH * IW; i += NT) {
        int ic = i / (IH * IW);
        int r  = (i / IW) % IH;
        int c  = i % IW;
        int ih = ih0 + r, iw = iw0 + c;
        float v = 0.f;
        if (ih >= 0 && ih < H && iw >= 0 && iw < W)
            v = in[(((size_t)n * IC + ic) * H + ih) * W + iw];
        s_in[ic][r][c] = v;
    }
    for (int i = tid; i < IC * 9 * OC; i += NT) s_w[i] = wt[i];
    __syncthreads();

    #pragma unroll
    for (int ic = 0; ic < IC; ic++) {
        #pragma unroll
        for (int kh = 0; kh < 3; kh++) {
            #pragma unroll
            for (int kw = 0; kw < 3; kw++) {
                float xv[4];
                #pragma unroll
                for (int p = 0; p < 4; p++)
                    xv[p] = s_in[ic][row * S + kh][(colq * 4 + p) * S + kw];
                const float4* wp =
                    reinterpret_cast<const float4*>(&s_w[(ic * 9 + kh * 3 + kw) * OC + ocg * 8]);
                float4 wa = wp[0], wb = wp[1];
                #pragma unroll
                for (int p = 0; p < 4; p++) {
                    acc[p][0] += xv[p] * wa.x; acc[p][1] += xv[p] * wa.y;
                    acc[p][2] += xv[p] * wa.z; acc[p][3] += xv[p] * wa.w;
                    acc[p][4] += xv[p] * wb.x; acc[p][5] += xv[p] * wb.y;
                    acc[p][6] += xv[p] * wb.z; acc[p][7] += xv[p] * wb.w;
                }
            }
        }
    }

    const int oh = blockIdx.y * TOH + row;
    const int ow = blockIdx.x * TOW + colq * 4;
    float bv[8];
    #pragma unroll
    for (int j = 0; j < 8; j++) bv[j] = bias[ocg * 8 + j];
    #pragma unroll
    for (int p = 0; p < 4; p++) {
        uint32_t pk[4];
        #pragma unroll
        for (int q = 0; q < 4; q++) {
            float lo = fmaxf(acc[p][2 * q]     + bv[2 * q],     0.f);
            float hi = fmaxf(acc[p][2 * q + 1] + bv[2 * q + 1], 0.f);
            pk[q] = pack_bf16x2(lo, hi);
        }
        size_t pix = ((size_t)n * OH + oh) * OW + (ow + p);
        *reinterpret_cast<uint4*>(&out[pix * 32 + ocg * 8]) =
            make_uint4(pk[0], pk[1], pk[2], pk[3]);
    }
}

// ---------------------------------------------------------------------------
// conv2/conv3: implicit GEMM via mma.sync (bf16 HMMA), NHWC bf16 in/out.
//   out[pix, oc] = relu(scale[oc] * sum_k A[pix,k]*sign[oc,k] + bias[oc])
// CTA: 256 threads = 8 warps (4 m-warps x 2 n-warps); tile = 128 px x OC.
// K processed in chunks of TAPS*IC; A im2col-staged, B sign chunk staged.
// ---------------------------------------------------------------------------
template<int IC, int OC, int H, int W, int S, int TAPS>
__global__ void __launch_bounds__(256, 2)
conv_mma(const __nv_bfloat16* __restrict__ in, __nv_bfloat16* __restrict__ out,
         const __nv_bfloat16* __restrict__ wsgn,
         const float* __restrict__ scale, const float* __restrict__ bias)
{
    constexpr int OH = (H - 1) / S + 1, OW = (W - 1) / S + 1;
    constexpr int K  = IC * 9;
    constexpr int KC = IC * TAPS;          // chunk K
    constexpr int NCHUNK = 9 / TAPS;
    constexpr int STEPS = KC / 16;
    constexpr int SAS = KC + 8;            // padded row stride (elements)
    constexpr int NF  = OC / 16;           // n8-fragments per warp (warp_n = OC/2)
    constexpr int AJ  = IC / 8;            // uint4 per (px,tap)

    __shared__ __align__(16) __nv_bfloat16 s_a[128 * SAS];
    __shared__ __align__(16) __nv_bfloat16 s_b[OC * SAS];
    __shared__ float s_scale[OC], s_bias[OC];

    const int tid  = threadIdx.x, wid = tid >> 5, lane = tid & 31;
    const int pix0 = blockIdx.x << 7;
    const int m0   = (wid & 3) * 32;
    const int n0   = (wid >> 2) * (OC / 2);

    if (tid < OC) { s_scale[tid] = scale[tid]; s_bias[tid] = bias[tid]; }

    float acc[2][NF][4];
    #pragma unroll
    for (int fm = 0; fm < 2; fm++)
        #pragma unroll
        for (int fn = 0; fn < NF; fn++)
            #pragma unroll
            for (int q = 0; q < 4; q++) acc[fm][fn][q] = 0.f;

    // ldmatrix lane-address bases
    const uint32_t a_base = smem_u32(s_a) +
        (uint32_t)(((m0 + (lane & 15)) * SAS + 8 * (lane >> 4)) * 2);
    const uint32_t b_base = smem_u32(s_b) +
        (uint32_t)((((lane & 7)) * SAS + 8 * ((lane >> 3) & 1)) * 2);

    for (int chunk = 0; chunk < NCHUNK; chunk++) {
        const int t0 = chunk * TAPS;
        // ---- stage A (im2col): 128 px x TAPS taps, IC contiguous bf16 each
        for (int i = tid; i < 128 * TAPS * AJ; i += 256) {
            int p    = i / (TAPS * AJ);
            int r    = i % (TAPS * AJ);
            int tapl = r / AJ, j = r % AJ;
            int tap  = t0 + tapl;
            int pix  = pix0 + p;
            int n    = pix / (OH * OW);
            int rem  = pix % (OH * OW);
            int oh   = rem / OW, ow = rem % OW;
            int ih   = oh * S + tap / 3 - 1;
            int iw   = ow * S + tap % 3 - 1;
            uint4 v = make_uint4(0, 0, 0, 0);
            if ((unsigned)ih < (unsigned)H && (unsigned)iw < (unsigned)W)
                v = reinterpret_cast<const uint4*>(
                        in + ((size_t)(n * H + ih) * W + iw) * IC)[j];
            *reinterpret_cast<uint4*>(&s_a[p * SAS + tapl * IC + j * 8]) = v;
        }
        // ---- stage B sign chunk: OC rows x KC cols
        for (int i = tid; i < OC * (KC / 8); i += 256) {
            int r  = i / (KC / 8);
            int k0 = (i % (KC / 8)) * 8;
            uint4 v = *reinterpret_cast<const uint4*>(
                wsgn + (size_t)r * K + t0 * IC + k0);
            *reinterpret_cast<uint4*>(&s_b[r * SAS + k0]) = v;
        }
        __syncthreads();

        // ---- MMA over chunk
        #pragma unroll
        for (int s = 0; s < STEPS; s++) {
            uint32_t a[2][4];
            ldmatrix_x4(a[0], a_base + (uint32_t)(s * 32));
            ldmatrix_x4(a[1], a_base + (uint32_t)(s * 32 + 16 * SAS * 2));
            uint32_t b[NF][2];
            #pragma unroll
            for (int fn = 0; fn < NF; fn++)
                ldmatrix_x2(b[fn], b_base + (uint32_t)(((n0 + fn * 8) * SAS) * 2 + s * 32));
            #pragma unroll
            for (int fm = 0; fm < 2; fm++)
                #pragma unroll
                for (int fn = 0; fn < NF; fn++)
                    mma16816(acc[fm][fn], a[fm], b[fn]);
        }
        __syncthreads();
    }

    // ---- epilogue: scale+bias+relu -> bf16 pairs, NHWC store
    #pragma unroll
    for (int fm = 0; fm < 2; fm++) {
        const int r0 = pix0 + m0 + fm * 16 + (lane >> 2);
        #pragma unroll
        for (int fn = 0; fn < NF; fn++) {
            const int oc = n0 + fn * 8 + 2 * (lane & 3);
            const float sc0 = s_scale[oc], sc1 = s_scale[oc + 1];
            const float bb0 = s_bias[oc],  bb1 = s_bias[oc + 1];
            const float* c = acc[fm][fn];
            uint32_t p0 = pack_bf16x2(fmaxf(c[0] * sc0 + bb0, 0.f),
                                      fmaxf(c[1] * sc1 + bb1, 0.f));
            uint32_t p1 = pack_bf16x2(fmaxf(c[2] * sc0 + bb0, 0.f),
                                      fmaxf(c[3] * sc1 + bb1, 0.f));
            *reinterpret_cast<uint32_t*>(out + (size_t)r0 * OC + oc)       = p0;
            *reinterpret_cast<uint32_t*>(out + (size_t)(r0 + 8) * OC + oc) = p1;
        }
    }
}

// ---------------------------------------------------------------------------
// Global average pool over NHWC bf16 [64][3136][128] -> fp32 g_pool[64][128]
// ---------------------------------------------------------------------------
__global__ void pool_nhwc(const __nv_bfloat16* __restrict__ h3)
{
    const int n = blockIdx.x, c = threadIdx.x;
    const __nv_bfloat16* p = h3 + (size_t)n * 3136 * 128 + c;
    float s = 0.f;
    #pragma unroll 8
    for (int i = 0; i < 3136; i++) s += __bfloat162float(p[(size_t)i * 128]);
    g_pool[n * 128 + c] = s * (1.f / 3136.f);
}

// ---------------------------------------------------------------------------
// Linear: out[n,j] = pool[n,:] . wlq[j,:] + bl[j]   (64x10)
// ---------------------------------------------------------------------------
__global__ void linear_kernel(const float* __restrict__ bl, float* __restrict__ out)
{
    int tid = blockIdx.x * blockDim.x + threadIdx.x;
    if (tid >= 640) return;
    int n = tid / 10, j = tid % 10;
    const float* hp = &g_pool[n * 128];
    const float* wp = &g_wlq[j * 128];
    float s = bl[j];
    #pragma unroll 8
    for (int c = 0; c < 128; c++) s += hp[c] * wp[c];
    out[tid] = s;
}

// ---------------------------------------------------------------------------
// Launch
// ---------------------------------------------------------------------------
extern "C" void kernel_launch(void* const* d_in, const int* in_sizes, int n_in,
                              void* d_out, int out_size)
{
    const float* x  = (const float*)d_in[0];
    const float* w1 = (const float*)d_in[1];
    const float* g1 = (const float*)d_in[2];
    const float* b1 = (const float*)d_in[3];
    const float* m1 = (const float*)d_in[4];
    const float* v1 = (const float*)d_in[5];
    const float* w2 = (const float*)d_in[6];
    const float* g2 = (const float*)d_in[7];
    const float* b2 = (const float*)d_in[8];
    const float* m2 = (const float*)d_in[9];
    const float* v2 = (const float*)d_in[10];
    const float* w3 = (const float*)d_in[11];
    const float* g3 = (const float*)d_in[12];
    const float* b3 = (const float*)d_in[13];
    const float* m3 = (const float*)d_in[14];
    const float* v3 = (const float*)d_in[15];
    const float* wl = (const float*)d_in[16];
    const float* bl = (const float*)d_in[17];

    __nv_bfloat16 *h1, *h2, *h3, *ws2, *ws3;
    float *w1t, *bb1, *sc2, *bb2, *sc3, *bb3;
    cudaGetSymbolAddress((void**)&h1,  g_h1);
    cudaGetSymbolAddress((void**)&h2,  g_h2);
    cudaGetSymbolAddress((void**)&h3,  g_h3);
    cudaGetSymbolAddress((void**)&ws2, g_wsgn2);
    cudaGetSymbolAddress((void**)&ws3, g_wsgn3);
    cudaGetSymbolAddress((void**)&w1t, g_w1t);
    cudaGetSymbolAddress((void**)&bb1, g_bias1);
    cudaGetSymbolAddress((void**)&sc2, g_scale2);
    cudaGetSymbolAddress((void**)&bb2, g_bias2);
    cudaGetSymbolAddress((void**)&sc3, g_scale3);
    cudaGetSymbolAddress((void**)&bb3, g_bias3);

    // 1. ternarize + fold
    prep_kernel<<<4, 256>>>(w1, g1, b1, m1, v1,
                            w2, g2, b2, m2, v2,
                            w3, g3, b3, m3, v3, wl);

    // 2. conv1: 3->32, s2, NCHW fp32 -> NHWC bf16
    conv1_kernel<<<dim3(7, 14, 64), 128>>>(x, h1, w1t, bb1);

    // 3. conv2: 32->64, s1 (implicit GEMM, K=288, 3-tap chunks)
    conv_mma<32, 64, 112, 112, 1, 3><<<6272, 256>>>(h1, h2, ws2, sc2, bb2);

    // 4. conv3: 64->128, s2 (implicit GEMM, K=576, 1-tap chunks)
    conv_mma<64, 128, 112, 112, 2, 1><<<1568, 256>>>(h2, h3, ws3, sc3, bb3);

    // 5. global average pool
    pool_nhwc<<<64, 128>>>(h3);

    // 6. linear head
    linear_kernel<<<3, 256>>>(bl, (float*)d_out);
}

// round 6
// speedup vs baseline: 5.9856x; 2.0359x over previous
#include <cuda_runtime.h>
#include <cuda_bf16.h>
#include <stdint.h>

#define BN_EPS 1e-5f

// ---------------------------------------------------------------------------
// Device-global scratch (no allocations allowed)
// ---------------------------------------------------------------------------
__device__ __nv_bfloat16 g_h1[(size_t)64 * 112 * 112 * 32];   // conv1 out, NHWC bf16
__device__ __nv_bfloat16 g_h2[(size_t)64 * 112 * 112 * 64];   // conv2 out, NHWC bf16
__device__ __nv_bfloat16 g_h3[(size_t)64 * 56 * 56 * 128];    // conv3 out, NHWC bf16
__device__ float         g_w1t[27 * 32];                      // conv1 folded fp32 [k][oc]
__device__ __nv_bfloat16 g_wsgn2[64 * 288];                   // conv2 signs [oc][k], k=tap*32+ic
__device__ __nv_bfloat16 g_wsgn3[128 * 576];                  // conv3 signs [oc][k], k=tap*64+ic
__device__ float g_bias1[32];
__device__ float g_scale2[64],  g_bias2[64];
__device__ float g_scale3[128], g_bias3[128];
__device__ float g_wlq[10 * 128];
__device__ float g_pool[64 * 128];
__device__ float g_poolpart[64 * 14 * 128];

// ---------------------------------------------------------------------------
// PTX helpers (base ISA only)
// ---------------------------------------------------------------------------
__device__ __forceinline__ uint32_t smem_u32(const void* p) {
    uint32_t a;
    asm("{ .reg .u64 t; cvta.to.shared.u64 t, %1; cvt.u32.u64 %0, t; }" : "=r"(a) : "l"(p));
    return a;
}
__device__ __forceinline__ void cp16(uint32_t dst, const void* src, bool ok) {
    int sz = ok ? 16 : 0;
    asm volatile("cp.async.cg.shared.global [%0], [%1], 16, %2;"
        :: "r"(dst), "l"(src), "r"(sz) : "memory");
}
__device__ __forceinline__ void ldmatrix_x4(uint32_t* r, uint32_t addr) {
    asm volatile("ldmatrix.sync.aligned.m8n8.x4.shared.b16 {%0,%1,%2,%3}, [%4];"
        : "=r"(r[0]), "=r"(r[1]), "=r"(r[2]), "=r"(r[3]) : "r"(addr));
}
__device__ __forceinline__ void ldmatrix_x2(uint32_t* r, uint32_t addr) {
    asm volatile("ldmatrix.sync.aligned.m8n8.x2.shared.b16 {%0,%1}, [%2];"
        : "=r"(r[0]), "=r"(r[1]) : "r"(addr));
}
__device__ __forceinline__ void mma16816(float* c, const uint32_t* a, const uint32_t* b) {
    asm volatile("mma.sync.aligned.m16n8k16.row.col.f32.bf16.bf16.f32 "
        "{%0,%1,%2,%3}, {%4,%5,%6,%7}, {%8,%9}, {%0,%1,%2,%3};"
        : "+f"(c[0]), "+f"(c[1]), "+f"(c[2]), "+f"(c[3])
        : "r"(a[0]), "r"(a[1]), "r"(a[2]), "r"(a[3]), "r"(b[0]), "r"(b[1]));
}
__device__ __forceinline__ uint32_t pack_bf16x2(float lo, float hi) {
    uint32_t r;
    asm("cvt.rn.bf16x2.f32 %0, %1, %2;" : "=r"(r) : "f"(hi), "f"(lo));
    return r;
}

// ---------------------------------------------------------------------------
// Block-wide sum reduction (256 threads)
// ---------------------------------------------------------------------------
__device__ __forceinline__ float block_reduce_sum(float v, float* sbuf) {
    int tid = threadIdx.x;
    #pragma unroll
    for (int o = 16; o > 0; o >>= 1) v += __shfl_down_sync(0xffffffffu, v, o);
    if ((tid & 31) == 0) sbuf[tid >> 5] = v;
    __syncthreads();
    float r = 0.f;
    if (tid == 0) {
        #pragma unroll
        for (int i = 0; i < 8; i++) r += sbuf[i];
        sbuf[0] = r;
    }
    __syncthreads();
    r = sbuf[0];
    __syncthreads();
    return r;
}

// ---------------------------------------------------------------------------
// Prep: ternarize weights, fold BN; sign matrices for conv2/3.
// ---------------------------------------------------------------------------
__global__ void prep_kernel(
    const float* __restrict__ w1, const float* __restrict__ g1, const float* __restrict__ b1,
    const float* __restrict__ m1, const float* __restrict__ v1,
    const float* __restrict__ w2, const float* __restrict__ g2, const float* __restrict__ b2,
    const float* __restrict__ m2, const float* __restrict__ v2,
    const float* __restrict__ w3, const float* __restrict__ g3, const float* __restrict__ b3,
    const float* __restrict__ m3, const float* __restrict__ v3,
    const float* __restrict__ wl)
{
    __shared__ float sbuf[8];
    const int t = blockIdx.x;
    const float* w; int n;
    if (t == 0)      { w = w1; n = 864;   }
    else if (t == 1) { w = w2; n = 18432; }
    else if (t == 2) { w = w3; n = 73728; }
    else             { w = wl; n = 1280;  }

    const int tid = threadIdx.x;

    float s = 0.f;
    for (int i = tid; i < n; i += blockDim.x) s += fabsf(w[i]);
    float tot = block_reduce_sum(s, sbuf);
    float delta = 0.7f * tot / (float)n;

    float ms = 0.f, cnt = 0.f;
    for (int i = tid; i < n; i += blockDim.x) {
        float a = fabsf(w[i]);
        if (a > delta) { ms += a; cnt += 1.f; }
    }
    float msum = block_reduce_sum(ms, sbuf);
    float csum = block_reduce_sum(cnt, sbuf);
    float alpha = msum / fmaxf(csum, 1.f);

    if (t == 0) {
        for (int i = tid; i < n; i += blockDim.x) {
            int o = i / 27, rem = i % 27;
            float wv = w[i];
            float q = (fabsf(wv) > delta) ? copysignf(alpha, wv) : 0.f;
            float inv = g1[o] * rsqrtf(v1[o] + BN_EPS);
            g_w1t[rem * 32 + o] = q * inv;
        }
        if (tid < 32) {
            float inv = g1[tid] * rsqrtf(v1[tid] + BN_EPS);
            g_bias1[tid] = b1[tid] - m1[tid] * inv;
        }
    } else if (t == 1) {
        for (int i = tid; i < 64 * 288; i += blockDim.x) {
            int o = i / 288, k = i % 288;
            int tap = k / 32, ic = k % 32;
            float wv = w2[o * 288 + ic * 9 + tap];
            float sv = (fabsf(wv) > delta) ? ((wv > 0.f) ? 1.f : -1.f) : 0.f;
            g_wsgn2[i] = __float2bfloat16(sv);
        }
        if (tid < 64) {
            float inv = g2[tid] * rsqrtf(v2[tid] + BN_EPS);
            g_scale2[tid] = alpha * inv;
            g_bias2[tid]  = b2[tid] - m2[tid] * inv;
        }
    } else if (t == 2) {
        for (int i = tid; i < 128 * 576; i += blockDim.x) {
            int o = i / 576, k = i % 576;
            int tap = k / 64, ic = k % 64;
            float wv = w3[o * 576 + ic * 9 + tap];
            float sv = (fabsf(wv) > delta) ? ((wv > 0.f) ? 1.f : -1.f) : 0.f;
            g_wsgn3[i] = __float2bfloat16(sv);
        }
        if (tid < 128) {
            float inv = g3[tid] * rsqrtf(v3[tid] + BN_EPS);
            g_scale3[tid] = alpha * inv;
            g_bias3[tid]  = b3[tid] - m3[tid] * inv;
        }
    } else {
        for (int i = tid; i < n; i += blockDim.x) {
            float wv = w[i];
            g_wlq[i] = (fabsf(wv) > delta) ? copysignf(alpha, wv) : 0.f;
        }
    }
}

// ---------------------------------------------------------------------------
// conv1: scalar fp32 direct 3x3 s2 (IC=3), NCHW fp32 in -> NHWC bf16 out
// ---------------------------------------------------------------------------
__global__ void conv1_kernel(const float* __restrict__ in, __nv_bfloat16* __restrict__ out,
                             const float* __restrict__ wt, const float* __restrict__ bias)
{
    constexpr int IC = 3, OC = 32, H = 224, W = 224, S = 2, TOH = 8, TOW = 16;
    constexpr int OH = 112, OW = 112;
    constexpr int IH = (TOH - 1) * S + 3;
    constexpr int IW = (TOW - 1) * S + 3;
    constexpr int COLQ = TOW / 4;
    constexpr int NT = 128;

    __shared__ float s_in[IC][IH][IW];
    __shared__ __align__(16) float s_w[IC * 9 * OC];

    const int tid  = threadIdx.x;
    const int ocg  = tid & 3;
    const int pg   = tid >> 2;
    const int row  = pg / COLQ;
    const int colq = pg % COLQ;
    const int n    = blockIdx.z;
    const int ih0  = blockIdx.y * TOH * S - 1;
    const int iw0  = blockIdx.x * TOW * S - 1;

    float acc[4][8];
    #pragma unroll
    for (int p = 0; p < 4; p++)
        #pragma unroll
        for (int j = 0; j < 8; j++) acc[p][j] = 0.f;

    for (int i = tid; i < IC * IH * IW; i += NT) {
        int ic = i / (IH * IW);
        int r  = (i / IW) % IH;
        int c  = i % IW;
        int ih = ih0 + r, iw = iw0 + c;
        float v = 0.f;
        if (ih >= 0 && ih < H && iw >= 0 && iw < W)
            v = in[(((size_t)n * IC + ic) * H + ih) * W + iw];
        s_in[ic][r][c] = v;
    }
    for (int i = tid; i < IC * 9 * OC; i += NT) s_w[i] = wt[i];
    __syncthreads();

    #pragma unroll
    for (int ic = 0; ic < IC; ic++) {
        #pragma unroll
        for (int kh = 0; kh < 3; kh++) {
            #pragma unroll
            for (int kw = 0; kw < 3; kw++) {
                float xv[4];
                #pragma unroll
                for (int p = 0; p < 4; p++)
                    xv[p] = s_in[ic][row * S + kh][(colq * 4 + p) * S + kw];
                const float4* wp =
                    reinterpret_cast<const float4*>(&s_w[(ic * 9 + kh * 3 + kw) * OC + ocg * 8]);
                float4 wa = wp[0], wb = wp[1];
                #pragma unroll
                for (int p = 0; p < 4; p++) {
                    acc[p][0] += xv[p] * wa.x; acc[p][1] += xv[p] * wa.y;
                    acc[p][2] += xv[p] * wa.z; acc[p][3] += xv[p] * wa.w;
                    acc[p][4] += xv[p] * wb.x; acc[p][5] += xv[p] * wb.y;
                    acc[p][6] += xv[p] * wb.z; acc[p][7] += xv[p] * wb.w;
                }
            }
        }
    }

    const int oh = blockIdx.y * TOH + row;
    const int ow = blockIdx.x * TOW + colq * 4;
    float bv[8];
    #pragma unroll
    for (int j = 0; j < 8; j++) bv[j] = bias[ocg * 8 + j];
    #pragma unroll
    for (int p = 0; p < 4; p++) {
        uint32_t pk[4];
        #pragma unroll
        for (int q = 0; q < 4; q++) {
            float lo = fmaxf(acc[p][2 * q]     + bv[2 * q],     0.f);
            float hi = fmaxf(acc[p][2 * q + 1] + bv[2 * q + 1], 0.f);
            pk[q] = pack_bf16x2(lo, hi);
        }
        size_t pix = ((size_t)n * OH + oh) * OW + (ow + p);
        *reinterpret_cast<uint4*>(&out[pix * 32 + ocg * 8]) =
            make_uint4(pk[0], pk[1], pk[2], pk[3]);
    }
}

// ---------------------------------------------------------------------------
// conv2/conv3: implicit GEMM via mma.sync, cp.async double-buffered pipeline.
//   out[pix, oc] = relu(scale[oc] * sum_k A[pix,k]*sign[oc,k] + bias[oc])
// CTA: 256 threads = 8 warps (4m x 2n); tile = 128 px x OC; K chunk = TAPS*IC.
// Dynamic smem: A[2][128*SAS] bf16, B[2][OC*SAS] bf16, scale/bias fp32.
// ---------------------------------------------------------------------------
template<int IC, int OC, int H, int W, int S, int TAPS>
__global__ void __launch_bounds__(256, 2)
conv_mma(const __nv_bfloat16* __restrict__ in, __nv_bfloat16* __restrict__ out,
         const __nv_bfloat16* __restrict__ wsgn,
         const float* __restrict__ scale, const float* __restrict__ bias)
{
    constexpr int OH = (H - 1) / S + 1, OW = (W - 1) / S + 1;
    constexpr int K  = IC * 9, KC = IC * TAPS, NCHUNK = 9 / TAPS, STEPS = KC / 16;
    constexpr int SAS = KC + 8;             // padded row stride (elements)
    constexpr int NF  = OC / 16, AJ = IC / 8, BJ = KC / 8;
    constexpr int ABYTES = 128 * SAS * 2, BBYTES = OC * SAS * 2;

    extern __shared__ char smem[];
    const uint32_t a_smem = smem_u32(smem);
    const uint32_t b_smem = a_smem + 2 * ABYTES;
    float* s_scale = reinterpret_cast<float*>(smem + 2 * ABYTES + 2 * BBYTES);
    float* s_bias  = s_scale + OC;

    const int tid  = threadIdx.x, wid = tid >> 5, lane = tid & 31;
    const int pix0 = blockIdx.x << 7;
    const int m0   = (wid & 3) * 32;
    const int n0   = (wid >> 2) * (OC / 2);

    if (tid < OC) { s_scale[tid] = scale[tid]; s_bias[tid] = bias[tid]; }

    auto stage = [&](int chunk) {
        const int buf = chunk & 1, t0 = chunk * TAPS;
        const uint32_t ab = a_smem + buf * ABYTES;
        #pragma unroll
        for (int i = tid; i < 128 * TAPS * AJ; i += 256) {
            int p    = i / (TAPS * AJ);
            int r    = i % (TAPS * AJ);
            int tapl = r / AJ, j = r % AJ;
            int tap  = t0 + tapl;
            int pix  = pix0 + p;
            int n    = pix / (OH * OW), rem = pix % (OH * OW);
            int oh   = rem / OW, ow = rem % OW;
            int ih   = oh * S + tap / 3 - 1;
            int iw   = ow * S + tap % 3 - 1;
            bool ok  = (unsigned)ih < (unsigned)H && (unsigned)iw < (unsigned)W;
            cp16(ab + (uint32_t)((p * SAS + tapl * IC + j * 8) * 2),
                 in + ((size_t)(n * H + ih) * W + iw) * IC + j * 8, ok);
        }
        const uint32_t bb = b_smem + buf * BBYTES;
        #pragma unroll
        for (int i = tid; i < OC * BJ; i += 256) {
            int rr = i / BJ, k0 = (i % BJ) * 8;
            cp16(bb + (uint32_t)((rr * SAS + k0) * 2),
                 wsgn + (size_t)rr * K + t0 * IC + k0, true);
        }
        asm volatile("cp.async.commit_group;" ::: "memory");
    };

    float acc[2][NF][4];
    #pragma unroll
    for (int fm = 0; fm < 2; fm++)
        #pragma unroll
        for (int fn = 0; fn < NF; fn++)
            #pragma unroll
            for (int q = 0; q < 4; q++) acc[fm][fn][q] = 0.f;

    const uint32_t a_off = (uint32_t)(((m0 + (lane & 15)) * SAS + 8 * (lane >> 4)) * 2);
    const uint32_t b_off = (uint32_t)(((lane & 7) * SAS + 8 * ((lane >> 3) & 1)) * 2);

    stage(0);
    for (int c = 0; c < NCHUNK; c++) {
        if (c + 1 < NCHUNK) {
            stage(c + 1);
            asm volatile("cp.async.wait_group 1;" ::: "memory");
        } else {
            asm volatile("cp.async.wait_group 0;" ::: "memory");
        }
        __syncthreads();

        const int buf = c & 1;
        const uint32_t abase = a_smem + buf * ABYTES + a_off;
        const uint32_t bbase = b_smem + buf * BBYTES + b_off;
        #pragma unroll
        for (int s = 0; s < STEPS; s++) {
            uint32_t a[2][4];
            ldmatrix_x4(a[0], abase + (uint32_t)(s * 32));
            ldmatrix_x4(a[1], abase + (uint32_t)(s * 32 + 16 * SAS * 2));
            uint32_t b[NF][2];
            #pragma unroll
            for (int fn = 0; fn < NF; fn++)
                ldmatrix_x2(b[fn], bbase + (uint32_t)((n0 + fn * 8) * SAS * 2 + s * 32));
            #pragma unroll
            for (int fm = 0; fm < 2; fm++)
                #pragma unroll
                for (int fn = 0; fn < NF; fn++)
                    mma16816(acc[fm][fn], a[fm], b[fn]);
        }
        __syncthreads();
    }

    // ---- epilogue: scale+bias+relu -> bf16 pairs, NHWC store
    #pragma unroll
    for (int fm = 0; fm < 2; fm++) {
        const int r0 = pix0 + m0 + fm * 16 + (lane >> 2);
        #pragma unroll
        for (int fn = 0; fn < NF; fn++) {
            const int oc = n0 + fn * 8 + 2 * (lane & 3);
            const float sc0 = s_scale[oc], sc1 = s_scale[oc + 1];
            const float bb0 = s_bias[oc],  bb1 = s_bias[oc + 1];
            const float* cc = acc[fm][fn];
            uint32_t p0 = pack_bf16x2(fmaxf(cc[0] * sc0 + bb0, 0.f),
                                      fmaxf(cc[1] * sc1 + bb1, 0.f));
            uint32_t p1 = pack_bf16x2(fmaxf(cc[2] * sc0 + bb0, 0.f),
                                      fmaxf(cc[3] * sc1 + bb1, 0.f));
            *reinterpret_cast<uint32_t*>(out + (size_t)r0 * OC + oc)       = p0;
            *reinterpret_cast<uint32_t*>(out + (size_t)(r0 + 8) * OC + oc) = p1;
        }
    }
}

// ---------------------------------------------------------------------------
// Global average pool, 2-stage deterministic. NHWC bf16 [64][3136][128].
// ---------------------------------------------------------------------------
__global__ void pool_stage1(const __nv_bfloat16* __restrict__ h3)
{
    const int n = blockIdx.x, sl = blockIdx.y, c = threadIdx.x;
    const __nv_bfloat16* p = h3 + ((size_t)n * 3136 + sl * 224) * 128 + c;
    float s = 0.f;
    #pragma unroll 8
    for (int i = 0; i < 224; i++) s += __bfloat162float(p[(size_t)i * 128]);
    g_poolpart[(n * 14 + sl) * 128 + c] = s;
}
__global__ void pool_stage2()
{
    const int n = blockIdx.x, c = threadIdx.x;
    float s = 0.f;
    #pragma unroll
    for (int i = 0; i < 14; i++) s += g_poolpart[(n * 14 + i) * 128 + c];
    g_pool[n * 128 + c] = s * (1.f / 3136.f);
}

// ---------------------------------------------------------------------------
// Linear: out[n,j] = pool[n,:] . wlq[j,:] + bl[j]   (64x10)
// ---------------------------------------------------------------------------
__global__ void linear_kernel(const float* __restrict__ bl, float* __restrict__ out)
{
    int tid = blockIdx.x * blockDim.x + threadIdx.x;
    if (tid >= 640) return;
    int n = tid / 10, j = tid % 10;
    const float* hp = &g_pool[n * 128];
    const float* wp = &g_wlq[j * 128];
    float s = bl[j];
    #pragma unroll 8
    for (int c = 0; c < 128; c++) s += hp[c] * wp[c];
    out[tid] = s;
}

// ---------------------------------------------------------------------------
// Launch
// ---------------------------------------------------------------------------
extern "C" void kernel_launch(void* const* d_in, const int* in_sizes, int n_in,
                              void* d_out, int out_size)
{
    const float* x  = (const float*)d_in[0];
    const float* w1 = (const float*)d_in[1];
    const float* g1 = (const float*)d_in[2];
    const float* b1 = (const float*)d_in[3];
    const float* m1 = (const float*)d_in[4];
    const float* v1 = (const float*)d_in[5];
    const float* w2 = (const float*)d_in[6];
    const float* g2 = (const float*)d_in[7];
    const float* b2 = (const float*)d_in[8];
    const float* m2 = (const float*)d_in[9];
    const float* v2 = (const float*)d_in[10];
    const float* w3 = (const float*)d_in[11];
    const float* g3 = (const float*)d_in[12];
    const float* b3 = (const float*)d_in[13];
    const float* m3 = (const float*)d_in[14];
    const float* v3 = (const float*)d_in[15];
    const float* wl = (const float*)d_in[16];
    const float* bl = (const float*)d_in[17];

    __nv_bfloat16 *h1, *h2, *h3, *ws2, *ws3;
    float *w1t, *bb1, *sc2, *bb2, *sc3, *bb3;
    cudaGetSymbolAddress((void**)&h1,  g_h1);
    cudaGetSymbolAddress((void**)&h2,  g_h2);
    cudaGetSymbolAddress((void**)&h3,  g_h3);
    cudaGetSymbolAddress((void**)&ws2, g_wsgn2);
    cudaGetSymbolAddress((void**)&ws3, g_wsgn3);
    cudaGetSymbolAddress((void**)&w1t, g_w1t);
    cudaGetSymbolAddress((void**)&bb1, g_bias1);
    cudaGetSymbolAddress((void**)&sc2, g_scale2);
    cudaGetSymbolAddress((void**)&bb2, g_bias2);
    cudaGetSymbolAddress((void**)&sc3, g_scale3);
    cudaGetSymbolAddress((void**)&bb3, g_bias3);

    // dynamic smem: 2*A + 2*B + scale/bias
    const int SM2 = 2 * (128 * 104 * 2) + 2 * (64 * 104 * 2) + 2 * 64 * 4;    // 80384
    const int SM3 = 2 * (128 * 72 * 2)  + 2 * (128 * 72 * 2) + 2 * 128 * 4;   // 74752
    cudaFuncSetAttribute(conv_mma<32, 64, 112, 112, 1, 3>,
                         cudaFuncAttributeMaxDynamicSharedMemorySize, SM2);
    cudaFuncSetAttribute(conv_mma<64, 128, 112, 112, 2, 1>,
                         cudaFuncAttributeMaxDynamicSharedMemorySize, SM3);

    // 1. ternarize + fold
    prep_kernel<<<4, 256>>>(w1, g1, b1, m1, v1,
                            w2, g2, b2, m2, v2,
                            w3, g3, b3, m3, v3, wl);

    // 2. conv1: 3->32, s2, NCHW fp32 -> NHWC bf16
    conv1_kernel<<<dim3(7, 14, 64), 128>>>(x, h1, w1t, bb1);

    // 3. conv2: 32->64, s1 (pipelined implicit GEMM, 3 chunks of K=96)
    conv_mma<32, 64, 112, 112, 1, 3><<<6272, 256, SM2>>>(h1, h2, ws2, sc2, bb2);

    // 4. conv3: 64->128, s2 (pipelined implicit GEMM, 9 chunks of K=64)
    conv_mma<64, 128, 112, 112, 2, 1><<<1568, 256, SM3>>>(h2, h3, ws3, sc3, bb3);

    // 5. global average pool (2-stage, deterministic)
    pool_stage1<<<dim3(64, 14), 128>>>(h3);
    pool_stage2<<<64, 128>>>();

    // 6. linear head
    linear_kernel<<<3, 256>>>(bl, (float*)d_out);
}